// round 14
// baseline (speedup 1.0000x reference)
#include <cuda_runtime.h>
#include <cuda_fp16.h>
#include <cuda_bf16.h>
#include <cstdint>

#define NN 50000
#define EE 800000
#define FULLMASK 0xffffffffu

// ---------------- device scratch ----------------
__device__ __align__(16) float  g_A[NN * 16];    // [0:8)=dst-side feats, [8:16)=src-side feats
__device__ __align__(16) __half g_Vh[NN * 128];  // H @ Wv  (fp16 storage)
__device__ __align__(16) float  g_Xres[NN * 128];// H @ Wres + b_res
__device__ __align__(16) float  g_AGG[NN * 128]; // normalized aggregated messages (tf32-rounded)
__device__ __align__(16) float  g_Ls[EE * 8];    // permuted per-edge exp(leaky(logit))
__device__ int   g_src2[EE];                     // permuted src ids
__device__ int   g_srcs[EE];
__device__ int   g_dsts[EE];
__device__ int   g_cnt[NN];
__device__ int   g_cursor[NN];
__device__ int   g_rowptr[NN + 1];
__device__ unsigned long long g_tileDesc[64];    // decoupled-lookback: (status<<32)|value
__device__ __align__(16) float g_M[128 * 16];
__device__ __align__(16) float g_w34[8];
__device__ int   g_flag = 0;                     // 0 => edge_index int64, else int32
__device__ __align__(16) float g_Wvt[128 * 128];
__device__ __align__(16) float g_Wrt[128 * 128];
__device__ __align__(16) float g_Wot[128 * 128];

// ---------------- tf32 / mma / cp.async helpers ----------------
__device__ __forceinline__ float tf32f(float x) {
    uint32_t r;
    asm("cvt.rna.tf32.f32 %0, %1;" : "=r"(r) : "f"(x));
    return __uint_as_float(r);
}
__device__ __forceinline__ void mma_tf32(float c[4], uint32_t a0, uint32_t a1,
                                         uint32_t a2, uint32_t a3,
                                         uint32_t b0, uint32_t b1) {
    asm volatile(
        "mma.sync.aligned.m16n8k8.row.col.f32.tf32.tf32.f32 "
        "{%0,%1,%2,%3}, {%4,%5,%6,%7}, {%8,%9}, {%0,%1,%2,%3};"
        : "+f"(c[0]), "+f"(c[1]), "+f"(c[2]), "+f"(c[3])
        : "r"(a0), "r"(a1), "r"(a2), "r"(a3), "r"(b0), "r"(b1));
}
__device__ __forceinline__ void ldm4(uint32_t r[4], uint32_t addr) {
    asm volatile("ldmatrix.sync.aligned.m8n8.x4.shared.b16 {%0,%1,%2,%3}, [%4];"
                 : "=r"(r[0]), "=r"(r[1]), "=r"(r[2]), "=r"(r[3]) : "r"(addr));
}
__device__ __forceinline__ void cpa16(void* smem, const void* gmem) {
    uint32_t s = (uint32_t)__cvta_generic_to_shared(smem);
    asm volatile("cp.async.cg.shared.global [%0], [%1], 16;" :: "r"(s), "l"(gmem));
}

// ---------------- setup ----------------
__global__ void k_setup(const int* __restrict__ ei32,
                        const float* __restrict__ W1, const float* __restrict__ W2,
                        const float* __restrict__ W3, const float* __restrict__ W4,
                        const float* __restrict__ Wv, const float* __restrict__ Wres,
                        const float* __restrict__ Wout) {
    int b = blockIdx.x, t = threadIdx.x;
    if (b < 196) {                       // zero g_cnt
        int i = b * 256 + t;
        if (i < NN) g_cnt[i] = 0;
    } else if (b < 200) {                // dtype detect + zero scan descriptors
        int i = (b - 196) * 256 + t;     // 0..1023
        if (ei32[2 * i + 1] != 0) atomicOr(&g_flag, 1);
        if (ei32[2 * (i + 400000) + 1] != 0) atomicOr(&g_flag, 1);
        if (b == 196 && t < 64) g_tileDesc[t] = 0ull;
    } else if (b < 208) {                // M = [W1@W4^T | W2@W4^T]
        int o = (b - 200) * 256 + t;     // 0..2047
        int k = o >> 4, j = o & 15;
        const float* wr = (j < 8) ? &W1[k * 128] : &W2[k * 128];
        const float* w4 = &W4[(j & 7) * 128];
        float s = 0.f;
        #pragma unroll 8
        for (int c = 0; c < 128; c++) s += wr[c] * w4[c];
        g_M[o] = s;
        if (b == 200 && t < 8) {
            const float* w4b = &W4[t * 128];
            float sw = 0.f;
            for (int c = 0; c < 128; c++) sw += W3[c] * w4b[c];
            g_w34[t] = sw;
        }
    } else {                             // weight tf32 (rna) preconversion
        int idx = (b - 208) * 256 + t;   // 0..49151
        int w = idx >> 14, off = idx & 16383;
        if (w == 0) g_Wvt[off] = tf32f(Wv[off]);
        else if (w == 1) g_Wrt[off] = tf32f(Wres[off]);
        else g_Wot[off] = tf32f(Wout[off]);
    }
}

// ---------------- pipelined tf32 GEMM core ----------------
// A-operand: raw f32 bits fed to HMMA.tf32 (HW uses the high 19 bits -> RZ
// rounding on A). B-operand: pre-rounded rna in setup / by aggregate.
struct GemmSmem {
    float As[2][128 * 20];   // [m][k] stride 20, BK=16
    float Bs[2][16 * 136];   // [k][n] stride 136
};

__device__ __forceinline__ void gemm_load_tile(GemmSmem* p, const float* __restrict__ Amat,
                                               const float* __restrict__ Bw,
                                               int m0, int mrows, int kt, int st) {
    const int tid = threadIdx.x;
    const int k0 = kt * 16;
    #pragma unroll
    for (int l = 0; l < 2; l++) {
        int flat = tid + l * 256;        // 0..511
        int m = flat >> 2, q = flat & 3;
        int row = min(m0 + m, mrows - 1);
        cpa16(&p->As[st][m * 20 + q * 4], &Amat[row * 128 + k0 + q * 4]);
    }
    #pragma unroll
    for (int l = 0; l < 2; l++) {
        int flat = tid + l * 256;
        int k = flat >> 5, q = flat & 31;
        cpa16(&p->Bs[st][k * 136 + q * 4], &Bw[(k0 + k) * 128 + q * 4]);
    }
}

// 256 threads = 8 warps (2 row x 4 col), warp tile 64x32; m0 = tile row base.
__device__ __forceinline__ void gemm_mma_pipe(GemmSmem* p, const float* __restrict__ Amat,
                                              const float* __restrict__ Bw,
                                              int m0, int mrows, float acc[4][4][4]) {
    const int tid = threadIdx.x;
    const int lane = tid & 31, wid = tid >> 5;
    const int m0w = (wid >> 2) * 64;
    const int n0w = (wid & 3) * 32;
    const int lrow = lane & 15;
    const int lcol = (lane >> 4) * 4;
    uint32_t asb[2];
    asb[0] = (uint32_t)__cvta_generic_to_shared(&p->As[0][(m0w + lrow) * 20 + lcol]);
    asb[1] = (uint32_t)__cvta_generic_to_shared(&p->As[1][(m0w + lrow) * 20 + lcol]);

    #pragma unroll
    for (int mt = 0; mt < 4; mt++)
        #pragma unroll
        for (int nt = 0; nt < 4; nt++)
            #pragma unroll
            for (int q = 0; q < 4; q++) acc[mt][nt][q] = 0.f;

    gemm_load_tile(p, Amat, Bw, m0, mrows, 0, 0);
    asm volatile("cp.async.commit_group;");

    #pragma unroll
    for (int kt = 0; kt < 8; kt++) {
        if (kt < 7) {
            gemm_load_tile(p, Amat, Bw, m0, mrows, kt + 1, (kt + 1) & 1);
            asm volatile("cp.async.commit_group;");
            asm volatile("cp.async.wait_group 1;");
        } else {
            asm volatile("cp.async.wait_group 0;");
        }
        __syncthreads();
        const int st = kt & 1;
        const float* bs = p->Bs[st];
        #pragma unroll
        for (int k8 = 0; k8 < 2; k8++) {
            const int kk = k8 * 8;
            uint32_t a[4][4];
            #pragma unroll
            for (int mt = 0; mt < 4; mt++)
                ldm4(a[mt], asb[st] + (uint32_t)((mt * 16 * 20 + kk) * 4));
            uint32_t b[4][2];
            #pragma unroll
            for (int nt = 0; nt < 4; nt++) {
                int n = n0w + nt * 8 + (lane >> 2);
                b[nt][0] = __float_as_uint(bs[(kk + (lane & 3)) * 136 + n]);
                b[nt][1] = __float_as_uint(bs[(kk + 4 + (lane & 3)) * 136 + n]);
            }
            #pragma unroll
            for (int mt = 0; mt < 4; mt++)
                #pragma unroll
                for (int nt = 0; nt < 4; nt++)
                    mma_tf32(acc[mt][nt], a[mt][0], a[mt][1], a[mt][2], a[mt][3],
                             b[nt][0], b[nt][1]);
        }
        __syncthreads();
    }
}

// ---------------- phase1: fused V-GEMM | Xres-GEMM | nodeA | edge_idx ----------------
#define P1_GEMM_BLKS 391
#define P1_NODEA0 (2 * P1_GEMM_BLKS)          // 782
#define P1_EDGE0  (P1_NODEA0 + 6250)          // 7032
#define P1_TOTAL  (P1_EDGE0 + 3125)           // 10157

__global__ void __launch_bounds__(256) k_phase1(const float* __restrict__ H,
                                                const float* __restrict__ b_res,
                                                const void* __restrict__ eiRaw) {
    __shared__ union { GemmSmem g; float Ms[128 * 17]; } sm;
    const int b = blockIdx.x;
    const int tid = threadIdx.x;

    if (b < P1_NODEA0) {
        // --- GEMM: V (b<391, fp16 output) or Xres (b>=391, fp32 output) ---
        const int y = (b >= P1_GEMM_BLKS);
        const int m0 = (y ? b - P1_GEMM_BLKS : b) * 128;
        const float* Bw = y ? g_Wrt : g_Wvt;

        float acc[4][4][4];
        gemm_mma_pipe(&sm.g, H, Bw, m0, NN, acc);

        const int lane = tid & 31, wid = tid >> 5;
        const int mr0 = m0 + (wid >> 2) * 64;
        const int n0 = (wid & 3) * 32;
        #pragma unroll
        for (int mt = 0; mt < 4; mt++) {
            int r0 = mr0 + mt * 16 + (lane >> 2);
            #pragma unroll
            for (int nt = 0; nt < 4; nt++) {
                int c = n0 + nt * 8 + 2 * (lane & 3);
                if (y) {
                    float b0 = b_res[c], b1 = b_res[c + 1];
                    if (r0 < NN)
                        *(float2*)&g_Xres[r0 * 128 + c] =
                            make_float2(acc[mt][nt][0] + b0, acc[mt][nt][1] + b1);
                    if (r0 + 8 < NN)
                        *(float2*)&g_Xres[(r0 + 8) * 128 + c] =
                            make_float2(acc[mt][nt][2] + b0, acc[mt][nt][3] + b1);
                } else {
                    if (r0 < NN)
                        *(__half2*)&g_Vh[r0 * 128 + c] =
                            __floats2half2_rn(acc[mt][nt][0], acc[mt][nt][1]);
                    if (r0 + 8 < NN)
                        *(__half2*)&g_Vh[(r0 + 8) * 128 + c] =
                            __floats2half2_rn(acc[mt][nt][2], acc[mt][nt][3]);
                }
            }
        }
    } else if (b < P1_EDGE0) {
        // --- nodeA: A = H @ M, warp per node ---
        for (int i = tid; i < 2048; i += 256) {
            int k = i >> 4, j = i & 15;
            sm.Ms[k * 17 + j] = g_M[i];
        }
        __syncthreads();
        int w = (b - P1_NODEA0) * 8 + (tid >> 5);
        int lane = tid & 31;
        if (w >= NN) return;
        float4 h4 = *(const float4*)&H[w * 128 + lane * 4];
        int kb = lane * 4;
        float myval = 0.f;
        #pragma unroll
        for (int j = 0; j < 16; j++) {
            float p = h4.x * sm.Ms[(kb + 0) * 17 + j] + h4.y * sm.Ms[(kb + 1) * 17 + j] +
                      h4.z * sm.Ms[(kb + 2) * 17 + j] + h4.w * sm.Ms[(kb + 3) * 17 + j];
            p += __shfl_xor_sync(FULLMASK, p, 16);
            p += __shfl_xor_sync(FULLMASK, p, 8);
            p += __shfl_xor_sync(FULLMASK, p, 4);
            p += __shfl_xor_sync(FULLMASK, p, 2);
            p += __shfl_xor_sync(FULLMASK, p, 1);
            if (lane == j) myval = p;
        }
        if (lane < 16) g_A[w * 16 + lane] = myval;
    } else {
        // --- edge_idx: index conversion + clamp + histogram ---
        int e = (b - P1_EDGE0) * 256 + tid;
        if (e >= EE) return;
        int s, d;
        if (g_flag == 0) {
            const long long* ei = (const long long*)eiRaw;
            s = (int)ei[e];
            d = (int)ei[EE + e];
        } else {
            const int* ei = (const int*)eiRaw;
            s = ei[e];
            d = ei[EE + e];
        }
        s = min(max(s, 0), NN - 1);
        d = min(max(d, 0), NN - 1);
        g_srcs[e] = s;
        g_dsts[e] = d;
        atomicAdd(&g_cnt[d], 1);
    }
}

// ---------------- single-pass scan (decoupled lookback), 49 blocks x 1024 ----------------
__global__ void k_scanOne() {
    __shared__ int sm[1024];
    __shared__ int s_excl;
    const int b = blockIdx.x, t = threadIdx.x;
    const int i = b * 1024 + t;
    int v = (i < NN) ? g_cnt[i] : 0;
    sm[t] = v;
    __syncthreads();
    for (int off = 1; off < 1024; off <<= 1) {
        int tv = 0;
        if (t >= (unsigned)off) tv = sm[t - off];
        __syncthreads();
        if (t >= (unsigned)off) sm[t] += tv;
        __syncthreads();
    }
    if (t == 0) {
        int blockAgg = sm[1023];
        if (b == 0) {
            atomicExch(&g_tileDesc[0], (2ull << 32) | (unsigned)blockAgg);
            s_excl = 0;
            g_flag = 0;   // reset dtype flag (consumed by this invocation's k_phase1)
        } else {
            atomicExch(&g_tileDesc[b], (1ull << 32) | (unsigned)blockAgg);
            int excl = 0;
            for (int j = b - 1;;) {
                unsigned long long d;
                do { d = atomicAdd(&g_tileDesc[j], 0ull); } while ((d >> 32) == 0);
                if ((d >> 32) == 2) { excl += (int)(unsigned)d; break; }
                excl += (int)(unsigned)d;
                j--;
            }
            atomicExch(&g_tileDesc[b], (2ull << 32) | (unsigned)(excl + blockAgg));
            s_excl = excl;
        }
    }
    __syncthreads();
    if (i < NN) {
        int excl = s_excl + sm[t] - v;
        g_rowptr[i] = excl;
        g_cursor[i] = excl;
        if (i == NN - 1) g_rowptr[NN] = excl + v;
    }
}

// fused scatter + logits + leakyrelu + exp: QUAD per edge (4 threads, 2 heads each).
// Lane r of the quad gathers 8B slices; lane 0 does the cursor atomic and
// broadcasts pos within the quad. Grid: EE*4/256 = 12500 blocks exactly.
__global__ void __launch_bounds__(256) k_scatter_logit(const float* __restrict__ P,
                                                       const float* __restrict__ det_) {
    int gt = blockIdx.x * 256 + threadIdx.x;
    int e = gt >> 2;            // edge id
    int r = gt & 3;             // quad sub-lane (heads 2r, 2r+1)
    int lane = threadIdx.x & 31;

    int s = g_srcs[e];
    int d = g_dsts[e];
    float p = P[e], dv = det_[e];
    float2 a1 = *(const float2*)&g_A[d * 16 + 2 * r];
    float2 a2 = *(const float2*)&g_A[s * 16 + 8 + 2 * r];
    float2 w34 = *(const float2*)&g_w34[2 * r];
    float l0 = a1.x + a2.x + p * w34.x + dv;
    float l1 = a1.y + a2.y + p * w34.y + dv;
    l0 = (l0 >= 0.f) ? l0 : 0.2f * l0;
    l1 = (l1 >= 0.f) ? l1 : 0.2f * l1;
    l0 = __expf(l0);
    l1 = __expf(l1);

    int pos = 0;
    if (r == 0) pos = atomicAdd(&g_cursor[d], 1);
    pos = __shfl_sync(FULLMASK, pos, lane & ~3);
    if (r == 0) g_src2[pos] = s;
    *(float2*)&g_Ls[pos * 8 + 2 * r] = make_float2(l0, l1);
}

// aggregation: warp per dst node; sequential weight/src reads, random fp16 V
// gathers. AGG stored pre-rounded to tf32 (rna) so out_gemm's A-path is exact rna.
__global__ void __launch_bounds__(256) k_aggregate() {
    int w = (blockIdx.x * blockDim.x + threadIdx.x) >> 5;
    int lane = threadIdx.x & 31;
    if (w >= NN) return;
    int i = g_rowptr[w];
    const int rp1 = g_rowptr[w + 1];
    const int head = lane >> 2;

    float4 acc = make_float4(0.f, 0.f, 0.f, 0.f);
    float ssum = 0.f;
    for (; i + 3 < rp1; i += 4) {
        int s0 = __ldg(&g_src2[i]);
        int s1 = __ldg(&g_src2[i + 1]);
        int s2 = __ldg(&g_src2[i + 2]);
        int s3 = __ldg(&g_src2[i + 3]);
        float w0 = __ldg(&g_Ls[i * 8 + head]);
        float w1 = __ldg(&g_Ls[(i + 1) * 8 + head]);
        float w2 = __ldg(&g_Ls[(i + 2) * 8 + head]);
        float w3 = __ldg(&g_Ls[(i + 3) * 8 + head]);
        uint2 r0 = *(const uint2*)&g_Vh[s0 * 128 + lane * 4];
        uint2 r1 = *(const uint2*)&g_Vh[s1 * 128 + lane * 4];
        uint2 r2 = *(const uint2*)&g_Vh[s2 * 128 + lane * 4];
        uint2 r3 = *(const uint2*)&g_Vh[s3 * 128 + lane * 4];
        float2 a0 = __half22float2(*(__half2*)&r0.x), b0 = __half22float2(*(__half2*)&r0.y);
        float2 a1 = __half22float2(*(__half2*)&r1.x), b1 = __half22float2(*(__half2*)&r1.y);
        float2 a2 = __half22float2(*(__half2*)&r2.x), b2 = __half22float2(*(__half2*)&r2.y);
        float2 a3 = __half22float2(*(__half2*)&r3.x), b3 = __half22float2(*(__half2*)&r3.y);
        acc.x += w0 * a0.x + w1 * a1.x + w2 * a2.x + w3 * a3.x;
        acc.y += w0 * a0.y + w1 * a1.y + w2 * a2.y + w3 * a3.y;
        acc.z += w0 * b0.x + w1 * b1.x + w2 * b2.x + w3 * b3.x;
        acc.w += w0 * b0.y + w1 * b1.y + w2 * b2.y + w3 * b3.y;
        ssum += (w0 + w1) + (w2 + w3);
    }
    for (; i < rp1; i++) {
        int s0 = __ldg(&g_src2[i]);
        float w0 = __ldg(&g_Ls[i * 8 + head]);
        uint2 r0 = *(const uint2*)&g_Vh[s0 * 128 + lane * 4];
        float2 a0 = __half22float2(*(__half2*)&r0.x), b0 = __half22float2(*(__half2*)&r0.y);
        acc.x += w0 * a0.x;
        acc.y += w0 * a0.y;
        acc.z += w0 * b0.x;
        acc.w += w0 * b0.y;
        ssum += w0;
    }
    float inv = 1.0f / (ssum + 1e-12f);
    *(float4*)&g_AGG[w * 128 + lane * 4] =
        make_float4(tf32f(acc.x * inv), tf32f(acc.y * inv),
                    tf32f(acc.z * inv), tf32f(acc.w * inv));
}

// output GEMM + bias + residual + fused LayerNorm -> final out
__global__ void __launch_bounds__(256) k_out_gemm(const float* __restrict__ b_out,
                                                  const float* __restrict__ gamma,
                                                  const float* __restrict__ beta,
                                                  float* __restrict__ out) {
    __shared__ union { GemmSmem g; float Xs[64 * 132]; } sm;
    const int m0 = blockIdx.x * 128;
    float acc[4][4][4];
    gemm_mma_pipe(&sm.g, g_AGG, g_Wot, m0, NN, acc);

    const int lane = threadIdx.x & 31, wid = threadIdx.x >> 5;
    const int warpRow = wid >> 2;
    const int n0 = (wid & 3) * 32;

    #pragma unroll
    for (int h = 0; h < 2; h++) {
        if (warpRow == h) {
            #pragma unroll
            for (int mt = 0; mt < 4; mt++) {
                int rl = mt * 16 + (lane >> 2);
                int gr0 = m0 + h * 64 + rl;
                #pragma unroll
                for (int nt = 0; nt < 4; nt++) {
                    int c = n0 + nt * 8 + 2 * (lane & 3);
                    float b0 = b_out[c], b1 = b_out[c + 1];
                    float2 xr0 = make_float2(0.f, 0.f), xr1 = make_float2(0.f, 0.f);
                    if (gr0 < NN) xr0 = *(const float2*)&g_Xres[gr0 * 128 + c];
                    if (gr0 + 8 < NN) xr1 = *(const float2*)&g_Xres[(gr0 + 8) * 128 + c];
                    *(float2*)&sm.Xs[rl * 132 + c] =
                        make_float2(acc[mt][nt][0] + b0 + xr0.x, acc[mt][nt][1] + b1 + xr0.y);
                    *(float2*)&sm.Xs[(rl + 8) * 132 + c] =
                        make_float2(acc[mt][nt][2] + b0 + xr1.x, acc[mt][nt][3] + b1 + xr1.y);
                }
            }
        }
        __syncthreads();
        #pragma unroll
        for (int rr = 0; rr < 8; rr++) {
            int rl = wid * 8 + rr;
            int gr = m0 + h * 64 + rl;
            float4 x = *(const float4*)&sm.Xs[rl * 132 + lane * 4];
            float p1 = x.x + x.y + x.z + x.w;
            float p2 = x.x * x.x + x.y * x.y + x.z * x.z + x.w * x.w;
            #pragma unroll
            for (int off = 16; off >= 1; off >>= 1) {
                p1 += __shfl_xor_sync(FULLMASK, p1, off);
                p2 += __shfl_xor_sync(FULLMASK, p2, off);
            }
            float mu = p1 * (1.f / 128.f);
            float var = p2 * (1.f / 128.f) - mu * mu;
            float rs = rsqrtf(var + 1e-5f);
            if (gr < NN) {
                float4 g = *(const float4*)&gamma[lane * 4];
                float4 b = *(const float4*)&beta[lane * 4];
                float4 o;
                o.x = (x.x - mu) * rs * g.x + b.x;
                o.y = (x.y - mu) * rs * g.y + b.y;
                o.z = (x.z - mu) * rs * g.z + b.z;
                o.w = (x.w - mu) * rs * g.w + b.w;
                *(float4*)&out[gr * 128 + lane * 4] = o;
            }
        }
        __syncthreads();
    }
}

// ---------------- launch ----------------
extern "C" void kernel_launch(void* const* d_in, const int* in_sizes, int n_in,
                              void* d_out, int out_size) {
    const float* H     = (const float*)d_in[0];
    const void*  ei    = d_in[1];
    const float* P     = (const float*)d_in[2];
    const float* det_  = (const float*)d_in[3];
    const float* W1    = (const float*)d_in[4];
    const float* W2    = (const float*)d_in[5];
    const float* W3    = (const float*)d_in[6];
    const float* W4    = (const float*)d_in[7];
    const float* Wv    = (const float*)d_in[8];
    const float* Wout  = (const float*)d_in[9];
    const float* b_out = (const float*)d_in[10];
    const float* Wres  = (const float*)d_in[11];
    const float* b_res = (const float*)d_in[12];
    const float* gamma = (const float*)d_in[13];
    const float* beta  = (const float*)d_in[14];
    float* out = (float*)d_out;

    k_setup<<<400, 256>>>((const int*)ei, W1, W2, W3, W4, Wv, Wres, Wout);
    k_phase1<<<P1_TOTAL, 256>>>(H, b_res, ei);
    k_scanOne<<<49, 1024>>>();
    k_scatter_logit<<<EE * 4 / 256, 256>>>(P, det_);
    k_aggregate<<<(NN * 32 + 255) / 256, 256>>>();
    k_out_gemm<<<(NN + 127) / 128, 256>>>(b_out, gamma, beta, out);
}

// round 16
// speedup vs baseline: 1.0664x; 1.0664x over previous
#include <cuda_runtime.h>
#include <cuda_fp16.h>
#include <cuda_bf16.h>
#include <cstdint>

#define NN 50000
#define EE 800000
#define FULLMASK 0xffffffffu

// ---------------- device scratch ----------------
__device__ __align__(16) float  g_A[NN * 16];    // [0:8)=dst-side feats, [8:16)=src-side feats
__device__ __align__(16) __half g_Vh[NN * 128];  // H @ Wv  (fp16 storage)
__device__ __align__(16) float  g_Xres[NN * 128];// H @ Wres + b_res
__device__ __align__(16) float  g_AGG[NN * 128]; // normalized aggregated messages
__device__ __align__(16) float  g_Ls[EE * 8];    // permuted per-edge exp(leaky(logit))
__device__ int   g_src2[EE];                     // permuted src ids
__device__ int   g_srcs[EE];
__device__ int   g_dsts[EE];
__device__ int   g_cnt[NN];
__device__ int   g_cursor[NN];
__device__ int   g_rowptr[NN + 1];
__device__ unsigned long long g_tileDesc[64];    // decoupled-lookback: (status<<32)|value
__device__ __align__(16) float g_M[128 * 16];
__device__ __align__(16) float g_w34[8];
__device__ int   g_flag = 0;                     // 0 => edge_index int64, else int32
__device__ __align__(16) float g_Wvt[128 * 128];
__device__ __align__(16) float g_Wrt[128 * 128];
__device__ __align__(16) float g_Wot[128 * 128];

// ---------------- tf32 / mma / cp.async helpers ----------------
__device__ __forceinline__ float tf32f(float x) {
    uint32_t r;
    asm("cvt.rna.tf32.f32 %0, %1;" : "=r"(r) : "f"(x));
    return __uint_as_float(r);
}
__device__ __forceinline__ uint32_t tf32u(uint32_t x) {
    uint32_t r;
    asm("cvt.rna.tf32.f32 %0, %1;" : "=r"(r) : "f"(__uint_as_float(x)));
    return r;
}
__device__ __forceinline__ void mma_tf32(float c[4], uint32_t a0, uint32_t a1,
                                         uint32_t a2, uint32_t a3,
                                         uint32_t b0, uint32_t b1) {
    asm volatile(
        "mma.sync.aligned.m16n8k8.row.col.f32.tf32.tf32.f32 "
        "{%0,%1,%2,%3}, {%4,%5,%6,%7}, {%8,%9}, {%0,%1,%2,%3};"
        : "+f"(c[0]), "+f"(c[1]), "+f"(c[2]), "+f"(c[3])
        : "r"(a0), "r"(a1), "r"(a2), "r"(a3), "r"(b0), "r"(b1));
}
__device__ __forceinline__ void ldm4(uint32_t r[4], uint32_t addr) {
    asm volatile("ldmatrix.sync.aligned.m8n8.x4.shared.b16 {%0,%1,%2,%3}, [%4];"
                 : "=r"(r[0]), "=r"(r[1]), "=r"(r[2]), "=r"(r[3]) : "r"(addr));
}
__device__ __forceinline__ void cpa16(void* smem, const void* gmem) {
    uint32_t s = (uint32_t)__cvta_generic_to_shared(smem);
    asm volatile("cp.async.cg.shared.global [%0], [%1], 16;" :: "r"(s), "l"(gmem));
}

// ---------------- setup ----------------
__global__ void k_setup(const int* __restrict__ ei32,
                        const float* __restrict__ W1, const float* __restrict__ W2,
                        const float* __restrict__ W3, const float* __restrict__ W4,
                        const float* __restrict__ Wv, const float* __restrict__ Wres,
                        const float* __restrict__ Wout) {
    int b = blockIdx.x, t = threadIdx.x;
    if (b < 196) {                       // zero g_cnt
        int i = b * 256 + t;
        if (i < NN) g_cnt[i] = 0;
    } else if (b < 200) {                // dtype detect + zero scan descriptors
        int i = (b - 196) * 256 + t;     // 0..1023
        if (ei32[2 * i + 1] != 0) atomicOr(&g_flag, 1);
        if (ei32[2 * (i + 400000) + 1] != 0) atomicOr(&g_flag, 1);
        if (b == 196 && t < 64) g_tileDesc[t] = 0ull;
    } else if (b < 208) {                // M = [W1@W4^T | W2@W4^T]
        int o = (b - 200) * 256 + t;     // 0..2047
        int k = o >> 4, j = o & 15;
        const float* wr = (j < 8) ? &W1[k * 128] : &W2[k * 128];
        const float* w4 = &W4[(j & 7) * 128];
        float s = 0.f;
        #pragma unroll 8
        for (int c = 0; c < 128; c++) s += wr[c] * w4[c];
        g_M[o] = s;
        if (b == 200 && t < 8) {
            const float* w4b = &W4[t * 128];
            float sw = 0.f;
            for (int c = 0; c < 128; c++) sw += W3[c] * w4b[c];
            g_w34[t] = sw;
        }
    } else {                             // weight tf32 (rna) preconversion
        int idx = (b - 208) * 256 + t;   // 0..49151
        int w = idx >> 14, off = idx & 16383;
        if (w == 0) g_Wvt[off] = tf32f(Wv[off]);
        else if (w == 1) g_Wrt[off] = tf32f(Wres[off]);
        else g_Wot[off] = tf32f(Wout[off]);
    }
}

// ---------------- pipelined tf32 GEMM core (rna cvt on A in-loop) ----------------
struct GemmSmem {
    float As[2][128 * 20];   // [m][k] stride 20, BK=16
    float Bs[2][16 * 136];   // [k][n] stride 136
};

__device__ __forceinline__ void gemm_load_tile(GemmSmem* p, const float* __restrict__ Amat,
                                               const float* __restrict__ Bw,
                                               int m0, int mrows, int kt, int st) {
    const int tid = threadIdx.x;
    const int k0 = kt * 16;
    #pragma unroll
    for (int l = 0; l < 2; l++) {
        int flat = tid + l * 256;        // 0..511
        int m = flat >> 2, q = flat & 3;
        int row = min(m0 + m, mrows - 1);
        cpa16(&p->As[st][m * 20 + q * 4], &Amat[row * 128 + k0 + q * 4]);
    }
    #pragma unroll
    for (int l = 0; l < 2; l++) {
        int flat = tid + l * 256;
        int k = flat >> 5, q = flat & 31;
        cpa16(&p->Bs[st][k * 136 + q * 4], &Bw[(k0 + k) * 128 + q * 4]);
    }
}

// 256 threads = 8 warps (2 row x 4 col), warp tile 64x32; m0 = tile row base.
__device__ __forceinline__ void gemm_mma_pipe(GemmSmem* p, const float* __restrict__ Amat,
                                              const float* __restrict__ Bw,
                                              int m0, int mrows, float acc[4][4][4]) {
    const int tid = threadIdx.x;
    const int lane = tid & 31, wid = tid >> 5;
    const int m0w = (wid >> 2) * 64;
    const int n0w = (wid & 3) * 32;
    const int lrow = lane & 15;
    const int lcol = (lane >> 4) * 4;
    uint32_t asb[2];
    asb[0] = (uint32_t)__cvta_generic_to_shared(&p->As[0][(m0w + lrow) * 20 + lcol]);
    asb[1] = (uint32_t)__cvta_generic_to_shared(&p->As[1][(m0w + lrow) * 20 + lcol]);

    #pragma unroll
    for (int mt = 0; mt < 4; mt++)
        #pragma unroll
        for (int nt = 0; nt < 4; nt++)
            #pragma unroll
            for (int q = 0; q < 4; q++) acc[mt][nt][q] = 0.f;

    gemm_load_tile(p, Amat, Bw, m0, mrows, 0, 0);
    asm volatile("cp.async.commit_group;");

    #pragma unroll
    for (int kt = 0; kt < 8; kt++) {
        if (kt < 7) {
            gemm_load_tile(p, Amat, Bw, m0, mrows, kt + 1, (kt + 1) & 1);
            asm volatile("cp.async.commit_group;");
            asm volatile("cp.async.wait_group 1;");
        } else {
            asm volatile("cp.async.wait_group 0;");
        }
        __syncthreads();
        const int st = kt & 1;
        const float* bs = p->Bs[st];
        #pragma unroll
        for (int k8 = 0; k8 < 2; k8++) {
            const int kk = k8 * 8;
            uint32_t a[4][4];
            #pragma unroll
            for (int mt = 0; mt < 4; mt++) {
                ldm4(a[mt], asb[st] + (uint32_t)((mt * 16 * 20 + kk) * 4));
                #pragma unroll
                for (int j = 0; j < 4; j++) a[mt][j] = tf32u(a[mt][j]);
            }
            uint32_t b[4][2];
            #pragma unroll
            for (int nt = 0; nt < 4; nt++) {
                int n = n0w + nt * 8 + (lane >> 2);
                b[nt][0] = __float_as_uint(bs[(kk + (lane & 3)) * 136 + n]);
                b[nt][1] = __float_as_uint(bs[(kk + 4 + (lane & 3)) * 136 + n]);
            }
            #pragma unroll
            for (int mt = 0; mt < 4; mt++)
                #pragma unroll
                for (int nt = 0; nt < 4; nt++)
                    mma_tf32(acc[mt][nt], a[mt][0], a[mt][1], a[mt][2], a[mt][3],
                             b[nt][0], b[nt][1]);
        }
        __syncthreads();
    }
}

// ---------------- phase1: fused V-GEMM | Xres-GEMM | nodeA | edge_idx ----------------
#define P1_GEMM_BLKS 391
#define P1_NODEA0 (2 * P1_GEMM_BLKS)          // 782
#define P1_EDGE0  (P1_NODEA0 + 6250)          // 7032
#define P1_TOTAL  (P1_EDGE0 + 3125)           // 10157

__global__ void __launch_bounds__(256) k_phase1(const float* __restrict__ H,
                                                const float* __restrict__ b_res,
                                                const void* __restrict__ eiRaw) {
    __shared__ union { GemmSmem g; float Ms[128 * 17]; } sm;
    const int b = blockIdx.x;
    const int tid = threadIdx.x;

    if (b < P1_NODEA0) {
        // --- GEMM: V (b<391, fp16 output) or Xres (b>=391, fp32 output) ---
        const int y = (b >= P1_GEMM_BLKS);
        const int m0 = (y ? b - P1_GEMM_BLKS : b) * 128;
        const float* Bw = y ? g_Wrt : g_Wvt;

        float acc[4][4][4];
        gemm_mma_pipe(&sm.g, H, Bw, m0, NN, acc);

        const int lane = tid & 31, wid = tid >> 5;
        const int mr0 = m0 + (wid >> 2) * 64;
        const int n0 = (wid & 3) * 32;
        #pragma unroll
        for (int mt = 0; mt < 4; mt++) {
            int r0 = mr0 + mt * 16 + (lane >> 2);
            #pragma unroll
            for (int nt = 0; nt < 4; nt++) {
                int c = n0 + nt * 8 + 2 * (lane & 3);
                if (y) {
                    float b0 = b_res[c], b1 = b_res[c + 1];
                    if (r0 < NN)
                        *(float2*)&g_Xres[r0 * 128 + c] =
                            make_float2(acc[mt][nt][0] + b0, acc[mt][nt][1] + b1);
                    if (r0 + 8 < NN)
                        *(float2*)&g_Xres[(r0 + 8) * 128 + c] =
                            make_float2(acc[mt][nt][2] + b0, acc[mt][nt][3] + b1);
                } else {
                    if (r0 < NN)
                        *(__half2*)&g_Vh[r0 * 128 + c] =
                            __floats2half2_rn(acc[mt][nt][0], acc[mt][nt][1]);
                    if (r0 + 8 < NN)
                        *(__half2*)&g_Vh[(r0 + 8) * 128 + c] =
                            __floats2half2_rn(acc[mt][nt][2], acc[mt][nt][3]);
                }
            }
        }
    } else if (b < P1_EDGE0) {
        // --- nodeA: A = H @ M, warp per node ---
        for (int i = tid; i < 2048; i += 256) {
            int k = i >> 4, j = i & 15;
            sm.Ms[k * 17 + j] = g_M[i];
        }
        __syncthreads();
        int w = (b - P1_NODEA0) * 8 + (tid >> 5);
        int lane = tid & 31;
        if (w >= NN) return;
        float4 h4 = *(const float4*)&H[w * 128 + lane * 4];
        int kb = lane * 4;
        float myval = 0.f;
        #pragma unroll
        for (int j = 0; j < 16; j++) {
            float p = h4.x * sm.Ms[(kb + 0) * 17 + j] + h4.y * sm.Ms[(kb + 1) * 17 + j] +
                      h4.z * sm.Ms[(kb + 2) * 17 + j] + h4.w * sm.Ms[(kb + 3) * 17 + j];
            p += __shfl_xor_sync(FULLMASK, p, 16);
            p += __shfl_xor_sync(FULLMASK, p, 8);
            p += __shfl_xor_sync(FULLMASK, p, 4);
            p += __shfl_xor_sync(FULLMASK, p, 2);
            p += __shfl_xor_sync(FULLMASK, p, 1);
            if (lane == j) myval = p;
        }
        if (lane < 16) g_A[w * 16 + lane] = myval;
    } else {
        // --- edge_idx: index conversion + clamp + histogram ---
        int e = (b - P1_EDGE0) * 256 + tid;
        if (e >= EE) return;
        int s, d;
        if (g_flag == 0) {
            const long long* ei = (const long long*)eiRaw;
            s = (int)ei[e];
            d = (int)ei[EE + e];
        } else {
            const int* ei = (const int*)eiRaw;
            s = ei[e];
            d = ei[EE + e];
        }
        s = min(max(s, 0), NN - 1);
        d = min(max(d, 0), NN - 1);
        g_srcs[e] = s;
        g_dsts[e] = d;
        atomicAdd(&g_cnt[d], 1);
    }
}

// ---------------- single-pass scan (decoupled lookback), 49 blocks x 1024 ----------------
__global__ void k_scanOne() {
    __shared__ int sm[1024];
    __shared__ int s_excl;
    const int b = blockIdx.x, t = threadIdx.x;
    const int i = b * 1024 + t;
    int v = (i < NN) ? g_cnt[i] : 0;
    sm[t] = v;
    __syncthreads();
    for (int off = 1; off < 1024; off <<= 1) {
        int tv = 0;
        if (t >= (unsigned)off) tv = sm[t - off];
        __syncthreads();
        if (t >= (unsigned)off) sm[t] += tv;
        __syncthreads();
    }
    if (t == 0) {
        int blockAgg = sm[1023];
        if (b == 0) {
            atomicExch(&g_tileDesc[0], (2ull << 32) | (unsigned)blockAgg);
            s_excl = 0;
            g_flag = 0;   // reset dtype flag (consumed by this invocation's k_phase1)
        } else {
            atomicExch(&g_tileDesc[b], (1ull << 32) | (unsigned)blockAgg);
            int excl = 0;
            for (int j = b - 1;;) {
                unsigned long long d;
                do { d = atomicAdd(&g_tileDesc[j], 0ull); } while ((d >> 32) == 0);
                if ((d >> 32) == 2) { excl += (int)(unsigned)d; break; }
                excl += (int)(unsigned)d;
                j--;
            }
            atomicExch(&g_tileDesc[b], (2ull << 32) | (unsigned)(excl + blockAgg));
            s_excl = excl;
        }
    }
    __syncthreads();
    if (i < NN) {
        int excl = s_excl + sm[t] - v;
        g_rowptr[i] = excl;
        g_cursor[i] = excl;
        if (i == NN - 1) g_rowptr[NN] = excl + v;
    }
}

// fused scatter + logits + leakyrelu + exp: QUAD per edge (4 threads, 2 heads each).
__global__ void __launch_bounds__(256) k_scatter_logit(const float* __restrict__ P,
                                                       const float* __restrict__ det_) {
    int gt = blockIdx.x * 256 + threadIdx.x;
    int e = gt >> 2;            // edge id
    int r = gt & 3;             // quad sub-lane (heads 2r, 2r+1)
    int lane = threadIdx.x & 31;

    int s = g_srcs[e];
    int d = g_dsts[e];
    float p = P[e], dv = det_[e];
    float2 a1 = *(const float2*)&g_A[d * 16 + 2 * r];
    float2 a2 = *(const float2*)&g_A[s * 16 + 8 + 2 * r];
    float2 w34 = *(const float2*)&g_w34[2 * r];
    float l0 = a1.x + a2.x + p * w34.x + dv;
    float l1 = a1.y + a2.y + p * w34.y + dv;
    l0 = (l0 >= 0.f) ? l0 : 0.2f * l0;
    l1 = (l1 >= 0.f) ? l1 : 0.2f * l1;
    l0 = __expf(l0);
    l1 = __expf(l1);

    int pos = 0;
    if (r == 0) pos = atomicAdd(&g_cursor[d], 1);
    pos = __shfl_sync(FULLMASK, pos, lane & ~3);
    if (r == 0) g_src2[pos] = s;
    *(float2*)&g_Ls[pos * 8 + 2 * r] = make_float2(l0, l1);
}

// aggregation: warp per dst node; sequential weight/src reads, random fp16 V gathers
__global__ void __launch_bounds__(256) k_aggregate() {
    int w = (blockIdx.x * blockDim.x + threadIdx.x) >> 5;
    int lane = threadIdx.x & 31;
    if (w >= NN) return;
    int i = g_rowptr[w];
    const int rp1 = g_rowptr[w + 1];
    const int head = lane >> 2;

    float4 acc = make_float4(0.f, 0.f, 0.f, 0.f);
    float ssum = 0.f;
    for (; i + 3 < rp1; i += 4) {
        int s0 = __ldg(&g_src2[i]);
        int s1 = __ldg(&g_src2[i + 1]);
        int s2 = __ldg(&g_src2[i + 2]);
        int s3 = __ldg(&g_src2[i + 3]);
        float w0 = __ldg(&g_Ls[i * 8 + head]);
        float w1 = __ldg(&g_Ls[(i + 1) * 8 + head]);
        float w2 = __ldg(&g_Ls[(i + 2) * 8 + head]);
        float w3 = __ldg(&g_Ls[(i + 3) * 8 + head]);
        uint2 r0 = *(const uint2*)&g_Vh[s0 * 128 + lane * 4];
        uint2 r1 = *(const uint2*)&g_Vh[s1 * 128 + lane * 4];
        uint2 r2 = *(const uint2*)&g_Vh[s2 * 128 + lane * 4];
        uint2 r3 = *(const uint2*)&g_Vh[s3 * 128 + lane * 4];
        float2 a0 = __half22float2(*(__half2*)&r0.x), b0 = __half22float2(*(__half2*)&r0.y);
        float2 a1 = __half22float2(*(__half2*)&r1.x), b1 = __half22float2(*(__half2*)&r1.y);
        float2 a2 = __half22float2(*(__half2*)&r2.x), b2 = __half22float2(*(__half2*)&r2.y);
        float2 a3 = __half22float2(*(__half2*)&r3.x), b3 = __half22float2(*(__half2*)&r3.y);
        acc.x += w0 * a0.x + w1 * a1.x + w2 * a2.x + w3 * a3.x;
        acc.y += w0 * a0.y + w1 * a1.y + w2 * a2.y + w3 * a3.y;
        acc.z += w0 * b0.x + w1 * b1.x + w2 * b2.x + w3 * b3.x;
        acc.w += w0 * b0.y + w1 * b1.y + w2 * b2.y + w3 * b3.y;
        ssum += (w0 + w1) + (w2 + w3);
    }
    for (; i < rp1; i++) {
        int s0 = __ldg(&g_src2[i]);
        float w0 = __ldg(&g_Ls[i * 8 + head]);
        uint2 r0 = *(const uint2*)&g_Vh[s0 * 128 + lane * 4];
        float2 a0 = __half22float2(*(__half2*)&r0.x), b0 = __half22float2(*(__half2*)&r0.y);
        acc.x += w0 * a0.x;
        acc.y += w0 * a0.y;
        acc.z += w0 * b0.x;
        acc.w += w0 * b0.y;
        ssum += w0;
    }
    float inv = 1.0f / (ssum + 1e-12f);
    *(float4*)&g_AGG[w * 128 + lane * 4] =
        make_float4(acc.x * inv, acc.y * inv, acc.z * inv, acc.w * inv);
}

// output GEMM + bias + residual + fused LayerNorm -> final out
__global__ void __launch_bounds__(256) k_out_gemm(const float* __restrict__ b_out,
                                                  const float* __restrict__ gamma,
                                                  const float* __restrict__ beta,
                                                  float* __restrict__ out) {
    __shared__ union { GemmSmem g; float Xs[64 * 132]; } sm;
    const int m0 = blockIdx.x * 128;
    float acc[4][4][4];
    gemm_mma_pipe(&sm.g, g_AGG, g_Wot, m0, NN, acc);

    const int lane = threadIdx.x & 31, wid = threadIdx.x >> 5;
    const int warpRow = wid >> 2;
    const int n0 = (wid & 3) * 32;

    #pragma unroll
    for (int h = 0; h < 2; h++) {
        if (warpRow == h) {
            #pragma unroll
            for (int mt = 0; mt < 4; mt++) {
                int rl = mt * 16 + (lane >> 2);
                int gr0 = m0 + h * 64 + rl;
                #pragma unroll
                for (int nt = 0; nt < 4; nt++) {
                    int c = n0 + nt * 8 + 2 * (lane & 3);
                    float b0 = b_out[c], b1 = b_out[c + 1];
                    float2 xr0 = make_float2(0.f, 0.f), xr1 = make_float2(0.f, 0.f);
                    if (gr0 < NN) xr0 = *(const float2*)&g_Xres[gr0 * 128 + c];
                    if (gr0 + 8 < NN) xr1 = *(const float2*)&g_Xres[(gr0 + 8) * 128 + c];
                    *(float2*)&sm.Xs[rl * 132 + c] =
                        make_float2(acc[mt][nt][0] + b0 + xr0.x, acc[mt][nt][1] + b1 + xr0.y);
                    *(float2*)&sm.Xs[(rl + 8) * 132 + c] =
                        make_float2(acc[mt][nt][2] + b0 + xr1.x, acc[mt][nt][3] + b1 + xr1.y);
                }
            }
        }
        __syncthreads();
        #pragma unroll
        for (int rr = 0; rr < 8; rr++) {
            int rl = wid * 8 + rr;
            int gr = m0 + h * 64 + rl;
            float4 x = *(const float4*)&sm.Xs[rl * 132 + lane * 4];
            float p1 = x.x + x.y + x.z + x.w;
            float p2 = x.x * x.x + x.y * x.y + x.z * x.z + x.w * x.w;
            #pragma unroll
            for (int off = 16; off >= 1; off >>= 1) {
                p1 += __shfl_xor_sync(FULLMASK, p1, off);
                p2 += __shfl_xor_sync(FULLMASK, p2, off);
            }
            float mu = p1 * (1.f / 128.f);
            float var = p2 * (1.f / 128.f) - mu * mu;
            float rs = rsqrtf(var + 1e-5f);
            if (gr < NN) {
                float4 g = *(const float4*)&gamma[lane * 4];
                float4 b = *(const float4*)&beta[lane * 4];
                float4 o;
                o.x = (x.x - mu) * rs * g.x + b.x;
                o.y = (x.y - mu) * rs * g.y + b.y;
                o.z = (x.z - mu) * rs * g.z + b.z;
                o.w = (x.w - mu) * rs * g.w + b.w;
                *(float4*)&out[gr * 128 + lane * 4] = o;
            }
        }
        __syncthreads();
    }
}

// ---------------- launch ----------------
extern "C" void kernel_launch(void* const* d_in, const int* in_sizes, int n_in,
                              void* d_out, int out_size) {
    const float* H     = (const float*)d_in[0];
    const void*  ei    = d_in[1];
    const float* P     = (const float*)d_in[2];
    const float* det_  = (const float*)d_in[3];
    const float* W1    = (const float*)d_in[4];
    const float* W2    = (const float*)d_in[5];
    const float* W3    = (const float*)d_in[6];
    const float* W4    = (const float*)d_in[7];
    const float* Wv    = (const float*)d_in[8];
    const float* Wout  = (const float*)d_in[9];
    const float* b_out = (const float*)d_in[10];
    const float* Wres  = (const float*)d_in[11];
    const float* b_res = (const float*)d_in[12];
    const float* gamma = (const float*)d_in[13];
    const float* beta  = (const float*)d_in[14];
    float* out = (float*)d_out;

    k_setup<<<400, 256>>>((const int*)ei, W1, W2, W3, W4, Wv, Wres, Wout);
    k_phase1<<<P1_TOTAL, 256>>>(H, b_res, ei);
    k_scanOne<<<49, 1024>>>();
    k_scatter_logit<<<EE * 4 / 256, 256>>>(P, det_);
    k_aggregate<<<(NN * 32 + 255) / 256, 256>>>();
    k_out_gemm<<<(NN + 127) / 128, 256>>>(b_out, gamma, beta, out);
}